// round 15
// baseline (speedup 1.0000x reference)
#include <cuda_runtime.h>
#include <cuda_bf16.h>
#include <cstdint>
#include <cstddef>

// Problem constants
#define CB 2
#define CT 1024
#define CC 2048
#define CH 16
#define CD 128
#define CP 1024
#define CL 2048   // P + T

// Scratch (allocation-free: device globals)
__device__ float g_q[(size_t)CB * CT * CC];    // Q projections, [B,T,C]
__device__ float g_att[(size_t)CB * CT * CC];  // attention output pre-projection

// ---------------------------------------------------------------------------
__device__ __forceinline__ uint32_t smem_to_u32(const void* smem_ptr) {
    uint32_t addr;
    asm("{ .reg .u64 tmp; cvta.to.shared.u64 tmp, %1; cvt.u32.u64 %0, tmp; }"
        : "=r"(addr) : "l"(smem_ptr));
    return addr;
}

// fp32 pair -> (hi bf16x2, lo bf16x2). low half = first element.
__device__ __forceinline__ void split2(float fx, float fy, uint32_t& hi, uint32_t& lo) {
    asm("cvt.rn.bf16x2.f32 %0, %1, %2;" : "=r"(hi) : "f"(fy), "f"(fx));
    float fxh = __uint_as_float(hi << 16);
    float fyh = __uint_as_float(hi & 0xffff0000u);
    float lx = fx - fxh;
    float ly = fy - fyh;
    asm("cvt.rn.bf16x2.f32 %0, %1, %2;" : "=r"(lo) : "f"(ly), "f"(lx));
}

__device__ __forceinline__ void ldsm_x4(uint32_t* r, uint32_t addr) {
    asm volatile("ldmatrix.sync.aligned.m8n8.x4.shared.b16 {%0,%1,%2,%3}, [%4];"
        : "=r"(r[0]), "=r"(r[1]), "=r"(r[2]), "=r"(r[3]) : "r"(addr));
}
__device__ __forceinline__ void ldsm_x4_t(uint32_t* r, uint32_t addr) {
    asm volatile("ldmatrix.sync.aligned.m8n8.x4.trans.shared.b16 {%0,%1,%2,%3}, [%4];"
        : "=r"(r[0]), "=r"(r[1]), "=r"(r[2]), "=r"(r[3]) : "r"(addr));
}

__device__ __forceinline__ void mma_bf16(float* c, const uint32_t* a,
                                         uint32_t b0, uint32_t b1) {
    asm volatile(
        "mma.sync.aligned.m16n8k16.row.col.f32.bf16.bf16.f32 "
        "{%0,%1,%2,%3}, {%4,%5,%6,%7}, {%8,%9}, {%0,%1,%2,%3};"
        : "+f"(c[0]), "+f"(c[1]), "+f"(c[2]), "+f"(c[3])
        : "r"(a[0]), "r"(a[1]), "r"(a[2]), "r"(a[3]), "r"(b0), "r"(b1));
}

// ---------------------------------------------------------------------------
// Copy past KV [B,H,P,D] into cache [B,H,L,D]
// ---------------------------------------------------------------------------
__global__ __launch_bounds__(256) void copy_past_kernel(
    const float* __restrict__ src, float* __restrict__ dst)
{
    const int PD4 = CP * CD / 4;
    const int LD4 = CL * CD / 4;
    int i = blockIdx.x * blockDim.x + threadIdx.x;
    int total = CB * CH * PD4;
    if (i < total) {
        int bh = i / PD4;
        int r = i - bh * PD4;
        reinterpret_cast<float4*>(dst)[(size_t)bh * LD4 + r] =
            reinterpret_cast<const float4*>(src)[i];
    }
}

// ---------------------------------------------------------------------------
// tf32 mma.sync helpers
// ---------------------------------------------------------------------------
__device__ __forceinline__ uint32_t f2tf(float f) {
    uint32_t u;
    asm("cvt.rna.tf32.f32 %0, %1;" : "=r"(u) : "f"(f));
    return u;
}

__device__ __forceinline__ void mma_tf32(
    float& c0, float& c1, float& c2, float& c3,
    uint32_t a0, uint32_t a1, uint32_t a2, uint32_t a3,
    uint32_t b0, uint32_t b1)
{
    asm volatile(
        "mma.sync.aligned.m16n8k8.row.col.f32.tf32.tf32.f32 "
        "{%0,%1,%2,%3}, {%4,%5,%6,%7}, {%8,%9}, {%0,%1,%2,%3};\n"
        : "+f"(c0), "+f"(c1), "+f"(c2), "+f"(c3)
        : "r"(a0), "r"(a1), "r"(a2), "r"(a3), "r"(b0), "r"(b1));
}

// ===========================================================================
// tf32 NT GEMM: Y[m,n] = sum_k A[m,k] * Bm[n,k]
// CTA tile 128(m) x 256(n), 256 threads = 8 warps (2x4), warp tile 64x64
// (acc[4][8][4] = 128 regs). Cuts A-fragment cross-warp redundancy 8x -> 4x:
// smem traffic/chunk 245KB -> ~176KB (crossbar was the binding resource).
// GPAD 36, K chunk 32, register prefetch, double-buffered smem, ldmatrix.
// Grid (8,16) = 128 CTAs = ONE wave.
// mode 0: plain | mode 1: +bias | mode 2: KV-cache scatter
// ===========================================================================
#define GPAD 36
#define ASTG (128 * GPAD)            // A stage: uint32 elems
#define BSTG (256 * GPAD)            // B stage: uint32 elems
#define STG_TOT (ASTG + BSTG)        // per double-buffer stage
#define GSMEM_BYTES (2 * STG_TOT * 4)   // 110592

__global__ __launch_bounds__(256, 1) void gemm_tf32_kernel(
    const float* __restrict__ A, const float* __restrict__ Bm,
    const float* __restrict__ bias, float* __restrict__ Y, int mode)
{
    extern __shared__ uint32_t smu[];
    // layout per stage: [A (128x36)][B (256x36)]
    const int tid = threadIdx.x;
    const int wid = tid >> 5;
    const int lane = tid & 31;
    const int g = lane >> 2;
    const int l4 = lane & 3;
    const int wr = wid >> 2;     // warp row 0..1 (64 m-rows each)
    const int wc = wid & 3;      // warp col 0..3 (64 n-cols each)
    const int m0 = blockIdx.y * 128;
    const int n0 = blockIdx.x * 256;

    // staging: float4 id = tid + it*256; row = id>>3, k4 = id&7
    const int srow = tid >> 3;   // 0..31
    const int sk4 = tid & 7;

    // ldmatrix per-lane bases
    const uint32_t subase = smem_to_u32(smu);
    const int laneRowA = (lane & 7) + ((lane >> 3) & 1) * 8;
    const int colSelA = (lane >> 4) * 4;
    const uint32_t baseAoff =
        (uint32_t)(((wr * 64 + laneRowA) * GPAD + colSelA) * 4);
    const int msel = (lane >> 3) & 3;
    const uint32_t baseBoff =
        (uint32_t)(((wc * 64 + (msel >> 1) * 8 + (lane & 7)) * GPAD
                    + (msel & 1) * 4) * 4 + ASTG * 4);

    float acc[4][8][4];
#pragma unroll
    for (int mt = 0; mt < 4; mt++)
#pragma unroll
        for (int nt = 0; nt < 8; nt++)
#pragma unroll
            for (int j = 0; j < 4; j++) acc[mt][nt][j] = 0.0f;

    float4 ra[4], rb[8];

    // ---- prologue: load + stage chunk 0 ----
#pragma unroll
    for (int it = 0; it < 4; it++) {
        int row = srow + it * 32;
        ra[it] = *reinterpret_cast<const float4*>(A + (size_t)(m0 + row) * CC + sk4 * 4);
    }
#pragma unroll
    for (int it = 0; it < 8; it++) {
        int row = srow + it * 32;
        rb[it] = *reinterpret_cast<const float4*>(Bm + (size_t)(n0 + row) * CC + sk4 * 4);
    }
    {
        uint32_t* As = smu;
        uint32_t* Bs = smu + ASTG;
#pragma unroll
        for (int it = 0; it < 4; it++) {
            int row = srow + it * 32;
            uint32_t* pa = As + row * GPAD + sk4 * 4;
            pa[0] = f2tf(ra[it].x); pa[1] = f2tf(ra[it].y);
            pa[2] = f2tf(ra[it].z); pa[3] = f2tf(ra[it].w);
        }
#pragma unroll
        for (int it = 0; it < 8; it++) {
            int row = srow + it * 32;
            uint32_t* pb = Bs + row * GPAD + sk4 * 4;
            pb[0] = f2tf(rb[it].x); pb[1] = f2tf(rb[it].y);
            pb[2] = f2tf(rb[it].z); pb[3] = f2tf(rb[it].w);
        }
    }
    __syncthreads();

    for (int c = 0; c < 64; c++) {
        // prefetch next chunk into registers
        if (c < 63) {
            const int k0 = (c + 1) * 32;
#pragma unroll
            for (int it = 0; it < 4; it++) {
                int row = srow + it * 32;
                ra[it] = *reinterpret_cast<const float4*>(
                    A + (size_t)(m0 + row) * CC + k0 + sk4 * 4);
            }
#pragma unroll
            for (int it = 0; it < 8; it++) {
                int row = srow + it * 32;
                rb[it] = *reinterpret_cast<const float4*>(
                    Bm + (size_t)(n0 + row) * CC + k0 + sk4 * 4);
            }
        }

        // compute on buffer c&1 (ldmatrix fragment loads)
        {
            const uint32_t sb = subase + (uint32_t)((c & 1) * STG_TOT * 4);
#pragma unroll
            for (int ks = 0; ks < 4; ks++) {
                uint32_t afr[4][4];
#pragma unroll
                for (int mt = 0; mt < 4; mt++)
                    ldsm_x4(afr[mt],
                            sb + baseAoff + (uint32_t)((mt * 16 * GPAD + ks * 8) * 4));
                uint32_t bfr[8][2];
#pragma unroll
                for (int p = 0; p < 4; p++) {
                    uint32_t t[4];
                    ldsm_x4(t, sb + baseBoff + (uint32_t)((p * 16 * GPAD + ks * 8) * 4));
                    bfr[2 * p][0] = t[0];     bfr[2 * p][1] = t[1];
                    bfr[2 * p + 1][0] = t[2]; bfr[2 * p + 1][1] = t[3];
                }
#pragma unroll
                for (int mt = 0; mt < 4; mt++)
#pragma unroll
                    for (int nt = 0; nt < 8; nt++)
                        mma_tf32(acc[mt][nt][0], acc[mt][nt][1],
                                 acc[mt][nt][2], acc[mt][nt][3],
                                 afr[mt][0], afr[mt][1], afr[mt][2], afr[mt][3],
                                 bfr[nt][0], bfr[nt][1]);
            }
        }

        // stage next chunk into the other buffer
        if (c < 63) {
            uint32_t* As = smu + ((c + 1) & 1) * STG_TOT;
            uint32_t* Bs = As + ASTG;
#pragma unroll
            for (int it = 0; it < 4; it++) {
                int row = srow + it * 32;
                uint32_t* pa = As + row * GPAD + sk4 * 4;
                pa[0] = f2tf(ra[it].x); pa[1] = f2tf(ra[it].y);
                pa[2] = f2tf(ra[it].z); pa[3] = f2tf(ra[it].w);
            }
#pragma unroll
            for (int it = 0; it < 8; it++) {
                int row = srow + it * 32;
                uint32_t* pb = Bs + row * GPAD + sk4 * 4;
                pb[0] = f2tf(rb[it].x); pb[1] = f2tf(rb[it].y);
                pb[2] = f2tf(rb[it].z); pb[3] = f2tf(rb[it].w);
            }
            __syncthreads();
        }
    }

    // ---- epilogue ----
#pragma unroll
    for (int mt = 0; mt < 4; mt++) {
        int row0 = m0 + wr * 64 + mt * 16 + g;
#pragma unroll
        for (int nt = 0; nt < 8; nt++) {
            int col0 = n0 + wc * 64 + nt * 8 + l4 * 2;
            float2 v01 = make_float2(acc[mt][nt][0], acc[mt][nt][1]);
            float2 v23 = make_float2(acc[mt][nt][2], acc[mt][nt][3]);
            if (mode == 1) {
                float b0 = bias[col0], b1 = bias[col0 + 1];
                v01.x += b0; v01.y += b1;
                v23.x += b0; v23.y += b1;
            }
            if (mode == 2) {
                int bb = row0 >> 10;
                int t = row0 & 1023;
                int h = col0 >> 7;
                int d = col0 & 127;
                float* base = Y + ((size_t)(bb * CH + h) * CL + CP + t) * CD + d;
                *reinterpret_cast<float2*>(base) = v01;
                *reinterpret_cast<float2*>(base + 8 * (size_t)CD) = v23;
            } else {
                float* base = Y + (size_t)row0 * CC + col0;
                *reinterpret_cast<float2*>(base) = v01;
                *reinterpret_cast<float2*>(base + 8 * (size_t)CC) = v23;
            }
        }
    }
}

// ===========================================================================
// bf16 split-3 mma flash attention. K-fragments via ldmatrix.x4.
// Long-first q-tile order: high-q0 CTAs (most key tiles) are scheduled in
// wave 1 so short CTAs fill the scheduling tail.
// ===========================================================================
#define QH_OFF 0
#define QL_OFF 32768
#define KH_OFF 65536
#define KL_OFF 81920
#define VH_OFF 98304
#define VL_OFF 114688
#define ATT_SMEM 131072

__global__ __launch_bounds__(256, 1) void attn_mma_kernel(
    const float* __restrict__ Qg,   // [B,T,C]
    const float* __restrict__ Kc,   // [B,H,L,D]
    const float* __restrict__ Vc,   // [B,H,L,D]
    float* __restrict__ Og)         // [B,T,C]
{
    extern __shared__ char sm[];
    const uint32_t su = smem_to_u32(sm);
    const int tid = threadIdx.x;
    const int wid = tid >> 5;
    const int lane = tid & 31;
    const int g = lane >> 2;
    const int l4 = lane & 3;
    const int lr = lane & 15;
    const int lc = lane >> 4;
    const int lx = lane & 7;
    const int bh = blockIdx.y;
    const int b = bh >> 4;
    const int h = bh & 15;
    const int q0 = (gridDim.x - 1 - blockIdx.x) * 128;   // long-first order
    const int qrow0 = wid * 16;

    // K-fragment ldmatrix per-lane constants
    const int msel = (lane >> 3) & 3;
    const int rowB = (msel >> 1) * 8 + (lane & 7);
    const int chunkAdd = msel & 1;

    // ---- stage Q (scaled, split bf16, swizzled) ----
    const float scale = 0.08838834764831845f;   // 1/sqrt(128)
#pragma unroll
    for (int it = 0; it < 16; it++) {
        int id = tid + it * 256;
        int row = id >> 5;
        int f4 = id & 31;
        int col = f4 * 4;
        float4 v = *reinterpret_cast<const float4*>(
            Qg + ((size_t)(b * CT + q0 + row)) * CC + h * CD + col);
        v.x *= scale; v.y *= scale; v.z *= scale; v.w *= scale;
        uint32_t h0, l0, h1, l1;
        split2(v.x, v.y, h0, l0);
        split2(v.z, v.w, h1, l1);
        uint32_t hidx = (uint32_t)(row * 128 + ((((col >> 3) ^ (row & 7)) << 3) | (col & 7)));
        *reinterpret_cast<uint2*>(sm + QH_OFF + 2 * hidx) = make_uint2(h0, h1);
        *reinterpret_cast<uint2*>(sm + QL_OFF + 2 * hidx) = make_uint2(l0, l1);
    }

    float o[16][4];
#pragma unroll
    for (int f = 0; f < 16; f++) { o[f][0] = o[f][1] = o[f][2] = o[f][3] = 0.0f; }
    float m0 = -1e30f, m1 = -1e30f, l0s = 0.0f, l1s = 0.0f;

    const float* Kbase = Kc + (size_t)bh * CL * CD;
    const float* Vbase = Vc + (size_t)bh * CL * CD;
    const int ntiles = (CP + q0 + 128) >> 6;

    for (int tI = 0; tI < ntiles; tI++) {
        const int j0 = tI * 64;
        __syncthreads();
#pragma unroll
        for (int it = 0; it < 8; it++) {
            int id = tid + it * 256;
            int row = id >> 5;
            int f4 = id & 31;
            int col = f4 * 4;
            uint32_t hidx = (uint32_t)(row * 128 + ((((col >> 3) ^ (row & 7)) << 3) | (col & 7)));
            float4 kv = *reinterpret_cast<const float4*>(
                Kbase + (size_t)(j0 + row) * CD + col);
            uint32_t h0, lo0, h1, lo1;
            split2(kv.x, kv.y, h0, lo0);
            split2(kv.z, kv.w, h1, lo1);
            *reinterpret_cast<uint2*>(sm + KH_OFF + 2 * hidx) = make_uint2(h0, h1);
            *reinterpret_cast<uint2*>(sm + KL_OFF + 2 * hidx) = make_uint2(lo0, lo1);
            float4 vv = *reinterpret_cast<const float4*>(
                Vbase + (size_t)(j0 + row) * CD + col);
            split2(vv.x, vv.y, h0, lo0);
            split2(vv.z, vv.w, h1, lo1);
            *reinterpret_cast<uint2*>(sm + VH_OFF + 2 * hidx) = make_uint2(h0, h1);
            *reinterpret_cast<uint2*>(sm + VL_OFF + 2 * hidx) = make_uint2(lo0, lo1);
        }
        __syncthreads();

        // ---- scores: S(16x64) = Q(16x128) K^T, 3-term split, ldmatrix K ----
        float s[8][4];
#pragma unroll
        for (int nf = 0; nf < 8; nf++) { s[nf][0] = s[nf][1] = s[nf][2] = s[nf][3] = 0.0f; }

#pragma unroll
        for (int kk = 0; kk < 8; kk++) {
            uint32_t qh[4], ql[4];
            uint32_t qidx = (uint32_t)((qrow0 + lr) * 128 + (((2 * kk + lc) ^ lx) << 3));
            ldsm_x4(qh, su + QH_OFF + 2 * qidx);
            ldsm_x4(ql, su + QL_OFF + 2 * qidx);
            uint32_t swoff = (uint32_t)((((2 * kk + chunkAdd) ^ (lane & 7)) << 3) * 2);
#pragma unroll
            for (int nfp = 0; nfp < 4; nfp++) {
                uint32_t off = (uint32_t)((nfp * 16 + rowB) * 256) + swoff;
                uint32_t tH[4], tL[4];
                ldsm_x4(tH, su + KH_OFF + off);
                ldsm_x4(tL, su + KL_OFF + off);
                mma_bf16(s[2 * nfp],     qh, tH[0], tH[1]);
                mma_bf16(s[2 * nfp],     qh, tL[0], tL[1]);
                mma_bf16(s[2 * nfp],     ql, tH[0], tH[1]);
                mma_bf16(s[2 * nfp + 1], qh, tH[2], tH[3]);
                mma_bf16(s[2 * nfp + 1], qh, tL[2], tL[3]);
                mma_bf16(s[2 * nfp + 1], ql, tH[2], tH[3]);
            }
        }

        // ---- causal mask ----
        if (j0 + 63 > CP + q0 + qrow0) {
            int rowa = CP + q0 + qrow0 + g;
#pragma unroll
            for (int nf = 0; nf < 8; nf++) {
                int colb = j0 + nf * 8 + 2 * l4;
                if (colb > rowa)         s[nf][0] = -1e30f;
                if (colb + 1 > rowa)     s[nf][1] = -1e30f;
                if (colb > rowa + 8)     s[nf][2] = -1e30f;
                if (colb + 1 > rowa + 8) s[nf][3] = -1e30f;
            }
        }

        // ---- online softmax ----
        float mx0 = -1e30f, mx1 = -1e30f;
#pragma unroll
        for (int nf = 0; nf < 8; nf++) {
            mx0 = fmaxf(mx0, fmaxf(s[nf][0], s[nf][1]));
            mx1 = fmaxf(mx1, fmaxf(s[nf][2], s[nf][3]));
        }
#pragma unroll
        for (int off = 1; off <= 2; off <<= 1) {
            mx0 = fmaxf(mx0, __shfl_xor_sync(0xffffffffu, mx0, off));
            mx1 = fmaxf(mx1, __shfl_xor_sync(0xffffffffu, mx1, off));
        }
        float m0n = fmaxf(m0, mx0);
        float m1n = fmaxf(m1, mx1);
        float a0 = __expf(m0 - m0n);
        float a1 = __expf(m1 - m1n);
        float sum0 = 0.0f, sum1 = 0.0f;
#pragma unroll
        for (int nf = 0; nf < 8; nf++) {
            s[nf][0] = __expf(s[nf][0] - m0n);
            s[nf][1] = __expf(s[nf][1] - m0n);
            s[nf][2] = __expf(s[nf][2] - m1n);
            s[nf][3] = __expf(s[nf][3] - m1n);
            sum0 += s[nf][0] + s[nf][1];
            sum1 += s[nf][2] + s[nf][3];
        }
#pragma unroll
        for (int off = 1; off <= 2; off <<= 1) {
            sum0 += __shfl_xor_sync(0xffffffffu, sum0, off);
            sum1 += __shfl_xor_sync(0xffffffffu, sum1, off);
        }
        l0s = l0s * a0 + sum0;
        l1s = l1s * a1 + sum1;
        m0 = m0n; m1 = m1n;
#pragma unroll
        for (int f = 0; f < 16; f++) {
            o[f][0] *= a0; o[f][1] *= a0;
            o[f][2] *= a1; o[f][3] *= a1;
        }

        // ---- PV ----
#pragma unroll
        for (int ks = 0; ks < 4; ks++) {
            uint32_t aph[4], apl[4];
            split2(s[2 * ks][0],     s[2 * ks][1],     aph[0], apl[0]);
            split2(s[2 * ks][2],     s[2 * ks][3],     aph[1], apl[1]);
            split2(s[2 * ks + 1][0], s[2 * ks + 1][1], aph[2], apl[2]);
            split2(s[2 * ks + 1][2], s[2 * ks + 1][3], aph[3], apl[3]);
            uint32_t vrow = (uint32_t)(ks * 16 + lr);
#pragma unroll
            for (int ds = 0; ds < 8; ds++) {
                uint32_t vidx = vrow * 128 + (uint32_t)((((ds * 2 + lc) ^ lx)) << 3);
                uint32_t vh[4], vl[4];
                ldsm_x4_t(vh, su + VH_OFF + 2 * vidx);
                ldsm_x4_t(vl, su + VL_OFF + 2 * vidx);
                mma_bf16(o[2 * ds],     aph, vh[0], vh[1]);
                mma_bf16(o[2 * ds + 1], aph, vh[2], vh[3]);
                mma_bf16(o[2 * ds],     aph, vl[0], vl[1]);
                mma_bf16(o[2 * ds + 1], aph, vl[2], vl[3]);
                mma_bf16(o[2 * ds],     apl, vh[0], vh[1]);
                mma_bf16(o[2 * ds + 1], apl, vh[2], vh[3]);
            }
        }
    }

    // ---- finalize + store ----
    float inv0 = 1.0f / l0s;
    float inv1 = 1.0f / l1s;
    int t0 = q0 + qrow0 + g;
    float* outr0 = Og + (size_t)(b * CT + t0) * CC + h * CD;
    float* outr1 = Og + (size_t)(b * CT + t0 + 8) * CC + h * CD;
#pragma unroll
    for (int nf = 0; nf < 16; nf++) {
        int d = nf * 8 + 2 * l4;
        *reinterpret_cast<float2*>(outr0 + d) = make_float2(o[nf][0] * inv0, o[nf][1] * inv0);
        *reinterpret_cast<float2*>(outr1 + d) = make_float2(o[nf][2] * inv1, o[nf][3] * inv1);
    }
}

// ---------------------------------------------------------------------------
extern "C" void kernel_launch(void* const* d_in, const int* in_sizes, int n_in,
                              void* d_out, int out_size)
{
    const float* x      = (const float*)d_in[0];
    const float* past_k = (const float*)d_in[1];
    const float* past_v = (const float*)d_in[2];
    const float* Wk     = (const float*)d_in[3];
    const float* Wq     = (const float*)d_in[4];
    const float* Wv     = (const float*)d_in[5];
    const float* Wp     = (const float*)d_in[6];
    const float* bp     = (const float*)d_in[7];

    float* out    = (float*)d_out;
    float* kcache = out + (size_t)CB * CT * CC;
    float* vcache = kcache + (size_t)CB * CH * CL * CD;

    float* qptr = nullptr;
    float* attptr = nullptr;
    cudaGetSymbolAddress((void**)&qptr, g_q);
    cudaGetSymbolAddress((void**)&attptr, g_att);

    // 1) copy past KV into cache regions of d_out
    int ncopy4 = CB * CH * CP * CD / 4;
    copy_past_kernel<<<(ncopy4 + 255) / 256, 256>>>(past_k, kcache);
    copy_past_kernel<<<(ncopy4 + 255) / 256, 256>>>(past_v, vcache);

    // 2) projections (tf32 mma.sync, 64x64 warp tiles, single wave)
    cudaFuncSetAttribute(gemm_tf32_kernel,
                         cudaFuncAttributeMaxDynamicSharedMemorySize, GSMEM_BYTES);
    dim3 ggrid(CC / 256, (CB * CT) / 128);   // (8, 16) = 128 CTAs
    gemm_tf32_kernel<<<ggrid, 256, GSMEM_BYTES>>>(x, Wq, nullptr, qptr, 0);
    gemm_tf32_kernel<<<ggrid, 256, GSMEM_BYTES>>>(x, Wk, nullptr, kcache, 2);
    gemm_tf32_kernel<<<ggrid, 256, GSMEM_BYTES>>>(x, Wv, nullptr, vcache, 2);

    // 3) attention (bf16 split-3 mma flash, long-first scheduling)
    cudaFuncSetAttribute(attn_mma_kernel,
                         cudaFuncAttributeMaxDynamicSharedMemorySize, ATT_SMEM);
    attn_mma_kernel<<<dim3(CT / 128, CB * CH), 256, ATT_SMEM>>>(
        qptr, kcache, vcache, attptr);

    // 4) output projection + bias
    gemm_tf32_kernel<<<ggrid, 256, GSMEM_BYTES>>>(attptr, Wp, bp, out, 1);
}

// round 16
// speedup vs baseline: 1.0800x; 1.0800x over previous
#include <cuda_runtime.h>
#include <cuda_bf16.h>
#include <cstdint>
#include <cstddef>

// Problem constants
#define CB 2
#define CT 1024
#define CC 2048
#define CH 16
#define CD 128
#define CP 1024
#define CL 2048   // P + T

// Scratch (allocation-free: device globals)
__device__ float g_q[(size_t)CB * CT * CC];    // Q projections, [B,T,C]
__device__ float g_att[(size_t)CB * CT * CC];  // attention output pre-projection

// ---------------------------------------------------------------------------
__device__ __forceinline__ uint32_t smem_to_u32(const void* smem_ptr) {
    uint32_t addr;
    asm("{ .reg .u64 tmp; cvta.to.shared.u64 tmp, %1; cvt.u32.u64 %0, tmp; }"
        : "=r"(addr) : "l"(smem_ptr));
    return addr;
}

// fp32 pair -> (hi bf16x2, lo bf16x2). low half = first element.
__device__ __forceinline__ void split2(float fx, float fy, uint32_t& hi, uint32_t& lo) {
    asm("cvt.rn.bf16x2.f32 %0, %1, %2;" : "=r"(hi) : "f"(fy), "f"(fx));
    float fxh = __uint_as_float(hi << 16);
    float fyh = __uint_as_float(hi & 0xffff0000u);
    float lx = fx - fxh;
    float ly = fy - fyh;
    asm("cvt.rn.bf16x2.f32 %0, %1, %2;" : "=r"(lo) : "f"(ly), "f"(lx));
}

__device__ __forceinline__ void ldsm_x4(uint32_t* r, uint32_t addr) {
    asm volatile("ldmatrix.sync.aligned.m8n8.x4.shared.b16 {%0,%1,%2,%3}, [%4];"
        : "=r"(r[0]), "=r"(r[1]), "=r"(r[2]), "=r"(r[3]) : "r"(addr));
}
__device__ __forceinline__ void ldsm_x4_t(uint32_t* r, uint32_t addr) {
    asm volatile("ldmatrix.sync.aligned.m8n8.x4.trans.shared.b16 {%0,%1,%2,%3}, [%4];"
        : "=r"(r[0]), "=r"(r[1]), "=r"(r[2]), "=r"(r[3]) : "r"(addr));
}

__device__ __forceinline__ void mma_bf16(float* c, const uint32_t* a,
                                         uint32_t b0, uint32_t b1) {
    asm volatile(
        "mma.sync.aligned.m16n8k16.row.col.f32.bf16.bf16.f32 "
        "{%0,%1,%2,%3}, {%4,%5,%6,%7}, {%8,%9}, {%0,%1,%2,%3};"
        : "+f"(c[0]), "+f"(c[1]), "+f"(c[2]), "+f"(c[3])
        : "r"(a[0]), "r"(a[1]), "r"(a[2]), "r"(a[3]), "r"(b0), "r"(b1));
}

// ---------------------------------------------------------------------------
// Copy past K and V [B,H,P,D] into caches [B,H,L,D] — one fused launch
// ---------------------------------------------------------------------------
__global__ __launch_bounds__(256) void copy_past_kernel(
    const float* __restrict__ srcK, const float* __restrict__ srcV,
    float* __restrict__ dstK, float* __restrict__ dstV)
{
    const int PD4 = CP * CD / 4;
    const int LD4 = CL * CD / 4;
    const int total = CB * CH * PD4;
    int i = blockIdx.x * blockDim.x + threadIdx.x;
    if (i < total) {
        int bh = i / PD4;
        int r = i - bh * PD4;
        reinterpret_cast<float4*>(dstK)[(size_t)bh * LD4 + r] =
            reinterpret_cast<const float4*>(srcK)[i];
    } else if (i < 2 * total) {
        int j = i - total;
        int bh = j / PD4;
        int r = j - bh * PD4;
        reinterpret_cast<float4*>(dstV)[(size_t)bh * LD4 + r] =
            reinterpret_cast<const float4*>(srcV)[j];
    }
}

// ---------------------------------------------------------------------------
// tf32 mma.sync helpers
// ---------------------------------------------------------------------------
__device__ __forceinline__ uint32_t f2tf(float f) {
    uint32_t u;
    asm("cvt.rna.tf32.f32 %0, %1;" : "=r"(u) : "f"(f));
    return u;
}

__device__ __forceinline__ void mma_tf32(
    float& c0, float& c1, float& c2, float& c3,
    uint32_t a0, uint32_t a1, uint32_t a2, uint32_t a3,
    uint32_t b0, uint32_t b1)
{
    asm volatile(
        "mma.sync.aligned.m16n8k8.row.col.f32.tf32.tf32.f32 "
        "{%0,%1,%2,%3}, {%4,%5,%6,%7}, {%8,%9}, {%0,%1,%2,%3};\n"
        : "+f"(c0), "+f"(c1), "+f"(c2), "+f"(c3)
        : "r"(a0), "r"(a1), "r"(a2), "r"(a3), "r"(b0), "r"(b1));
}

// ===========================================================================
// tf32 NT GEMM — exact R12 configuration (proven 107us):
// CTA 128x256, 512 threads = 16 warps (2x8), warp tile 64x32, GPAD 36,
// K chunk 32, register prefetch, double-buffered smem, ldmatrix frags.
// Grid (8,16) = 128 CTAs = ONE wave.
// mode 0: plain | mode 1: +bias | mode 2: KV-cache scatter
// ===========================================================================
#define GPAD 36
#define ASTG (128 * GPAD)
#define BSTG (256 * GPAD)
#define STG_TOT (ASTG + BSTG)
#define GSMEM_BYTES (2 * STG_TOT * 4)   // 110592

__global__ __launch_bounds__(512, 1) void gemm_tf32_kernel(
    const float* __restrict__ A, const float* __restrict__ Bm,
    const float* __restrict__ bias, float* __restrict__ Y, int mode)
{
    extern __shared__ uint32_t smu[];
    const int tid = threadIdx.x;
    const int wid = tid >> 5;
    const int lane = tid & 31;
    const int g = lane >> 2;
    const int l4 = lane & 3;
    const int wr = wid >> 3;
    const int wc = wid & 7;
    const int m0 = blockIdx.y * 128;
    const int n0 = blockIdx.x * 256;

    const int srow = tid >> 3;
    const int sk4 = tid & 7;

    const uint32_t subase = smem_to_u32(smu);
    const int laneRowA = (lane & 7) + ((lane >> 3) & 1) * 8;
    const int colSelA = (lane >> 4) * 4;
    const uint32_t baseAoff =
        (uint32_t)(((wr * 64 + laneRowA) * GPAD + colSelA) * 4);
    const int msel = (lane >> 3) & 3;
    const uint32_t baseBoff =
        (uint32_t)(((wc * 32 + (msel >> 1) * 8 + (lane & 7)) * GPAD
                    + (msel & 1) * 4) * 4 + ASTG * 4);

    float acc[4][4][4];
#pragma unroll
    for (int mt = 0; mt < 4; mt++)
#pragma unroll
        for (int nt = 0; nt < 4; nt++)
#pragma unroll
            for (int j = 0; j < 4; j++) acc[mt][nt][j] = 0.0f;

    float4 ra[2], rb[4];

#pragma unroll
    for (int it = 0; it < 2; it++) {
        int row = srow + it * 64;
        ra[it] = *reinterpret_cast<const float4*>(A + (size_t)(m0 + row) * CC + sk4 * 4);
    }
#pragma unroll
    for (int it = 0; it < 4; it++) {
        int row = srow + it * 64;
        rb[it] = *reinterpret_cast<const float4*>(Bm + (size_t)(n0 + row) * CC + sk4 * 4);
    }
    {
        uint32_t* As = smu;
        uint32_t* Bs = smu + ASTG;
#pragma unroll
        for (int it = 0; it < 2; it++) {
            int row = srow + it * 64;
            uint32_t* pa = As + row * GPAD + sk4 * 4;
            pa[0] = f2tf(ra[it].x); pa[1] = f2tf(ra[it].y);
            pa[2] = f2tf(ra[it].z); pa[3] = f2tf(ra[it].w);
        }
#pragma unroll
        for (int it = 0; it < 4; it++) {
            int row = srow + it * 64;
            uint32_t* pb = Bs + row * GPAD + sk4 * 4;
            pb[0] = f2tf(rb[it].x); pb[1] = f2tf(rb[it].y);
            pb[2] = f2tf(rb[it].z); pb[3] = f2tf(rb[it].w);
        }
    }
    __syncthreads();

    for (int c = 0; c < 64; c++) {
        if (c < 63) {
            const int k0 = (c + 1) * 32;
#pragma unroll
            for (int it = 0; it < 2; it++) {
                int row = srow + it * 64;
                ra[it] = *reinterpret_cast<const float4*>(
                    A + (size_t)(m0 + row) * CC + k0 + sk4 * 4);
            }
#pragma unroll
            for (int it = 0; it < 4; it++) {
                int row = srow + it * 64;
                rb[it] = *reinterpret_cast<const float4*>(
                    Bm + (size_t)(n0 + row) * CC + k0 + sk4 * 4);
            }
        }

        {
            const uint32_t sb = subase + (uint32_t)((c & 1) * STG_TOT * 4);
#pragma unroll
            for (int ks = 0; ks < 4; ks++) {
                uint32_t afr[4][4];
#pragma unroll
                for (int mt = 0; mt < 4; mt++)
                    ldsm_x4(afr[mt],
                            sb + baseAoff + (uint32_t)((mt * 16 * GPAD + ks * 8) * 4));
                uint32_t bfr[4][2];
#pragma unroll
                for (int p = 0; p < 2; p++) {
                    uint32_t t[4];
                    ldsm_x4(t, sb + baseBoff + (uint32_t)((p * 16 * GPAD + ks * 8) * 4));
                    bfr[2 * p][0] = t[0];     bfr[2 * p][1] = t[1];
                    bfr[2 * p + 1][0] = t[2]; bfr[2 * p + 1][1] = t[3];
                }
#pragma unroll
                for (int mt = 0; mt < 4; mt++)
#pragma unroll
                    for (int nt = 0; nt < 4; nt++)
                        mma_tf32(acc[mt][nt][0], acc[mt][nt][1],
                                 acc[mt][nt][2], acc[mt][nt][3],
                                 afr[mt][0], afr[mt][1], afr[mt][2], afr[mt][3],
                                 bfr[nt][0], bfr[nt][1]);
            }
        }

        if (c < 63) {
            uint32_t* As = smu + ((c + 1) & 1) * STG_TOT;
            uint32_t* Bs = As + ASTG;
#pragma unroll
            for (int it = 0; it < 2; it++) {
                int row = srow + it * 64;
                uint32_t* pa = As + row * GPAD + sk4 * 4;
                pa[0] = f2tf(ra[it].x); pa[1] = f2tf(ra[it].y);
                pa[2] = f2tf(ra[it].z); pa[3] = f2tf(ra[it].w);
            }
#pragma unroll
            for (int it = 0; it < 4; it++) {
                int row = srow + it * 64;
                uint32_t* pb = Bs + row * GPAD + sk4 * 4;
                pb[0] = f2tf(rb[it].x); pb[1] = f2tf(rb[it].y);
                pb[2] = f2tf(rb[it].z); pb[3] = f2tf(rb[it].w);
            }
            __syncthreads();
        }
    }

#pragma unroll
    for (int mt = 0; mt < 4; mt++) {
        int row0 = m0 + wr * 64 + mt * 16 + g;
#pragma unroll
        for (int nt = 0; nt < 4; nt++) {
            int col0 = n0 + wc * 32 + nt * 8 + l4 * 2;
            float2 v01 = make_float2(acc[mt][nt][0], acc[mt][nt][1]);
            float2 v23 = make_float2(acc[mt][nt][2], acc[mt][nt][3]);
            if (mode == 1) {
                float b0 = bias[col0], b1 = bias[col0 + 1];
                v01.x += b0; v01.y += b1;
                v23.x += b0; v23.y += b1;
            }
            if (mode == 2) {
                int bb = row0 >> 10;
                int t = row0 & 1023;
                int h = col0 >> 7;
                int d = col0 & 127;
                float* base = Y + ((size_t)(bb * CH + h) * CL + CP + t) * CD + d;
                *reinterpret_cast<float2*>(base) = v01;
                *reinterpret_cast<float2*>(base + 8 * (size_t)CD) = v23;
            } else {
                float* base = Y + (size_t)row0 * CC + col0;
                *reinterpret_cast<float2*>(base) = v01;
                *reinterpret_cast<float2*>(base + 8 * (size_t)CC) = v23;
            }
        }
    }
}

// ===========================================================================
// Flash attention: tf32 single-pass QK (m16n8k8) + bf16 split-3 PV.
// Q/K staged as tf32 in 132-word padded rows (same bank residue as GPAD 36,
// conflict-free ldmatrix); V staged as split bf16 (unchanged).
// Long-first q-tile order.
// ===========================================================================
#define QSTRIDE 132
#define QT_OFF 0                          // Q: 128 x 132 tf32 = 67584 B
#define KT_OFF 67584                      // K: 64 x 132 tf32 = 33792 B
#define VH_OFF 101376                     // V hi: 16384 B
#define VL_OFF 117760                     // V lo: 16384 B
#define ATT_SMEM 134144

__global__ __launch_bounds__(256, 1) void attn_mma_kernel(
    const float* __restrict__ Qg,   // [B,T,C]
    const float* __restrict__ Kc,   // [B,H,L,D]
    const float* __restrict__ Vc,   // [B,H,L,D]
    float* __restrict__ Og)         // [B,T,C]
{
    extern __shared__ char sm[];
    const uint32_t su = smem_to_u32(sm);
    const int tid = threadIdx.x;
    const int wid = tid >> 5;
    const int lane = tid & 31;
    const int g = lane >> 2;
    const int l4 = lane & 3;
    const int lr = lane & 15;
    const int lc = lane >> 4;
    const int lx = lane & 7;
    const int bh = blockIdx.y;
    const int b = bh >> 4;
    const int h = bh & 15;
    const int q0 = (gridDim.x - 1 - blockIdx.x) * 128;   // long-first order
    const int qrow0 = wid * 16;

    // tf32 fragment addressing (same mapping as the GEMM)
    const int msel = (lane >> 3) & 3;
    const int laneRowA = (lane & 7) + ((lane >> 3) & 1) * 8;
    const int colSelA = (lane >> 4) * 4;
    const int rowB = (msel >> 1) * 8 + (lane & 7);
    const uint32_t qfragbase = su + QT_OFF +
        (uint32_t)(((qrow0 + laneRowA) * QSTRIDE + colSelA) * 4);
    const uint32_t kfragbase = su + KT_OFF +
        (uint32_t)((rowB * QSTRIDE + (msel & 1) * 4) * 4);

    // ---- stage Q (scaled tf32, padded rows) ----
    const float scale = 0.08838834764831845f;   // 1/sqrt(128)
#pragma unroll
    for (int it = 0; it < 16; it++) {
        int id = tid + it * 256;
        int row = id >> 5;
        int col = (id & 31) * 4;
        float4 v = *reinterpret_cast<const float4*>(
            Qg + ((size_t)(b * CT + q0 + row)) * CC + h * CD + col);
        uint4 w = make_uint4(f2tf(v.x * scale), f2tf(v.y * scale),
                             f2tf(v.z * scale), f2tf(v.w * scale));
        *reinterpret_cast<uint4*>(sm + QT_OFF + (size_t)(row * QSTRIDE + col) * 4) = w;
    }

    float o[16][4];
#pragma unroll
    for (int f = 0; f < 16; f++) { o[f][0] = o[f][1] = o[f][2] = o[f][3] = 0.0f; }
    float m0 = -1e30f, m1 = -1e30f, l0s = 0.0f, l1s = 0.0f;

    const float* Kbase = Kc + (size_t)bh * CL * CD;
    const float* Vbase = Vc + (size_t)bh * CL * CD;
    const int ntiles = (CP + q0 + 128) >> 6;

    for (int tI = 0; tI < ntiles; tI++) {
        const int j0 = tI * 64;
        __syncthreads();
        // ---- stage K (tf32) + V (split bf16, swizzled) ----
#pragma unroll
        for (int it = 0; it < 8; it++) {
            int id = tid + it * 256;
            int row = id >> 5;          // 0..63
            int col = (id & 31) * 4;
            float4 kv = *reinterpret_cast<const float4*>(
                Kbase + (size_t)(j0 + row) * CD + col);
            uint4 kw = make_uint4(f2tf(kv.x), f2tf(kv.y), f2tf(kv.z), f2tf(kv.w));
            *reinterpret_cast<uint4*>(sm + KT_OFF + (size_t)(row * QSTRIDE + col) * 4) = kw;

            uint32_t hidx = (uint32_t)(row * 128 + ((((col >> 3) ^ (row & 7)) << 3) | (col & 7)));
            float4 vv = *reinterpret_cast<const float4*>(
                Vbase + (size_t)(j0 + row) * CD + col);
            uint32_t h0, lo0, h1, lo1;
            split2(vv.x, vv.y, h0, lo0);
            split2(vv.z, vv.w, h1, lo1);
            *reinterpret_cast<uint2*>(sm + VH_OFF + 2 * hidx) = make_uint2(h0, h1);
            *reinterpret_cast<uint2*>(sm + VL_OFF + 2 * hidx) = make_uint2(lo0, lo1);
        }
        __syncthreads();

        // ---- scores: S(16x64) = Q(16x128) K^T, tf32 single-pass ----
        float s[8][4];
#pragma unroll
        for (int nf = 0; nf < 8; nf++) { s[nf][0] = s[nf][1] = s[nf][2] = s[nf][3] = 0.0f; }

#pragma unroll
        for (int ks = 0; ks < 16; ks++) {
            uint32_t qf[4];
            ldsm_x4(qf, qfragbase + (uint32_t)(ks * 32));
#pragma unroll
            for (int nfp = 0; nfp < 4; nfp++) {
                uint32_t t[4];
                ldsm_x4(t, kfragbase + (uint32_t)((nfp * 16 * QSTRIDE + ks * 8) * 4));
                mma_tf32(s[2 * nfp][0], s[2 * nfp][1], s[2 * nfp][2], s[2 * nfp][3],
                         qf[0], qf[1], qf[2], qf[3], t[0], t[1]);
                mma_tf32(s[2 * nfp + 1][0], s[2 * nfp + 1][1],
                         s[2 * nfp + 1][2], s[2 * nfp + 1][3],
                         qf[0], qf[1], qf[2], qf[3], t[2], t[3]);
            }
        }

        // ---- causal mask ----
        if (j0 + 63 > CP + q0 + qrow0) {
            int rowa = CP + q0 + qrow0 + g;
#pragma unroll
            for (int nf = 0; nf < 8; nf++) {
                int colb = j0 + nf * 8 + 2 * l4;
                if (colb > rowa)         s[nf][0] = -1e30f;
                if (colb + 1 > rowa)     s[nf][1] = -1e30f;
                if (colb > rowa + 8)     s[nf][2] = -1e30f;
                if (colb + 1 > rowa + 8) s[nf][3] = -1e30f;
            }
        }

        // ---- online softmax (rows g, g+8; quad-local reductions) ----
        float mx0 = -1e30f, mx1 = -1e30f;
#pragma unroll
        for (int nf = 0; nf < 8; nf++) {
            mx0 = fmaxf(mx0, fmaxf(s[nf][0], s[nf][1]));
            mx1 = fmaxf(mx1, fmaxf(s[nf][2], s[nf][3]));
        }
#pragma unroll
        for (int off = 1; off <= 2; off <<= 1) {
            mx0 = fmaxf(mx0, __shfl_xor_sync(0xffffffffu, mx0, off));
            mx1 = fmaxf(mx1, __shfl_xor_sync(0xffffffffu, mx1, off));
        }
        float m0n = fmaxf(m0, mx0);
        float m1n = fmaxf(m1, mx1);
        float a0 = __expf(m0 - m0n);
        float a1 = __expf(m1 - m1n);
        float sum0 = 0.0f, sum1 = 0.0f;
#pragma unroll
        for (int nf = 0; nf < 8; nf++) {
            s[nf][0] = __expf(s[nf][0] - m0n);
            s[nf][1] = __expf(s[nf][1] - m0n);
            s[nf][2] = __expf(s[nf][2] - m1n);
            s[nf][3] = __expf(s[nf][3] - m1n);
            sum0 += s[nf][0] + s[nf][1];
            sum1 += s[nf][2] + s[nf][3];
        }
#pragma unroll
        for (int off = 1; off <= 2; off <<= 1) {
            sum0 += __shfl_xor_sync(0xffffffffu, sum0, off);
            sum1 += __shfl_xor_sync(0xffffffffu, sum1, off);
        }
        l0s = l0s * a0 + sum0;
        l1s = l1s * a1 + sum1;
        m0 = m0n; m1 = m1n;
#pragma unroll
        for (int f = 0; f < 16; f++) {
            o[f][0] *= a0; o[f][1] *= a0;
            o[f][2] *= a1; o[f][3] *= a1;
        }

        // ---- PV: O(16x128) += P(16x64) V(64x128), bf16 split-3 ----
#pragma unroll
        for (int ks = 0; ks < 4; ks++) {
            uint32_t aph[4], apl[4];
            split2(s[2 * ks][0],     s[2 * ks][1],     aph[0], apl[0]);
            split2(s[2 * ks][2],     s[2 * ks][3],     aph[1], apl[1]);
            split2(s[2 * ks + 1][0], s[2 * ks + 1][1], aph[2], apl[2]);
            split2(s[2 * ks + 1][2], s[2 * ks + 1][3], aph[3], apl[3]);
            uint32_t vrow = (uint32_t)(ks * 16 + lr);
#pragma unroll
            for (int ds = 0; ds < 8; ds++) {
                uint32_t vidx = vrow * 128 + (uint32_t)((((ds * 2 + lc) ^ lx)) << 3);
                uint32_t vh[4], vl[4];
                ldsm_x4_t(vh, su + VH_OFF + 2 * vidx);
                ldsm_x4_t(vl, su + VL_OFF + 2 * vidx);
                mma_bf16(o[2 * ds],     aph, vh[0], vh[1]);
                mma_bf16(o[2 * ds + 1], aph, vh[2], vh[3]);
                mma_bf16(o[2 * ds],     aph, vl[0], vl[1]);
                mma_bf16(o[2 * ds + 1], aph, vl[2], vl[3]);
                mma_bf16(o[2 * ds],     apl, vh[0], vh[1]);
                mma_bf16(o[2 * ds + 1], apl, vh[2], vh[3]);
            }
        }
    }

    // ---- finalize + store ----
    float inv0 = 1.0f / l0s;
    float inv1 = 1.0f / l1s;
    int t0 = q0 + qrow0 + g;
    float* outr0 = Og + (size_t)(b * CT + t0) * CC + h * CD;
    float* outr1 = Og + (size_t)(b * CT + t0 + 8) * CC + h * CD;
#pragma unroll
    for (int nf = 0; nf < 16; nf++) {
        int d = nf * 8 + 2 * l4;
        *reinterpret_cast<float2*>(outr0 + d) = make_float2(o[nf][0] * inv0, o[nf][1] * inv0);
        *reinterpret_cast<float2*>(outr1 + d) = make_float2(o[nf][2] * inv1, o[nf][3] * inv1);
    }
}

// ---------------------------------------------------------------------------
extern "C" void kernel_launch(void* const* d_in, const int* in_sizes, int n_in,
                              void* d_out, int out_size)
{
    const float* x      = (const float*)d_in[0];
    const float* past_k = (const float*)d_in[1];
    const float* past_v = (const float*)d_in[2];
    const float* Wk     = (const float*)d_in[3];
    const float* Wq     = (const float*)d_in[4];
    const float* Wv     = (const float*)d_in[5];
    const float* Wp     = (const float*)d_in[6];
    const float* bp     = (const float*)d_in[7];

    float* out    = (float*)d_out;
    float* kcache = out + (size_t)CB * CT * CC;
    float* vcache = kcache + (size_t)CB * CH * CL * CD;

    float* qptr = nullptr;
    float* attptr = nullptr;
    cudaGetSymbolAddress((void**)&qptr, g_q);
    cudaGetSymbolAddress((void**)&attptr, g_att);

    // 1) copy past KV into cache regions of d_out (fused K+V)
    int ncopy4 = CB * CH * CP * CD / 4;
    copy_past_kernel<<<(2 * ncopy4 + 255) / 256, 256>>>(past_k, past_v, kcache, vcache);

    // 2) projections (tf32 mma.sync, R12 config, single wave)
    cudaFuncSetAttribute(gemm_tf32_kernel,
                         cudaFuncAttributeMaxDynamicSharedMemorySize, GSMEM_BYTES);
    dim3 ggrid(CC / 256, (CB * CT) / 128);   // (8, 16) = 128 CTAs
    gemm_tf32_kernel<<<ggrid, 512, GSMEM_BYTES>>>(x, Wq, nullptr, qptr, 0);
    gemm_tf32_kernel<<<ggrid, 512, GSMEM_BYTES>>>(x, Wk, nullptr, kcache, 2);
    gemm_tf32_kernel<<<ggrid, 512, GSMEM_BYTES>>>(x, Wv, nullptr, vcache, 2);

    // 3) attention (tf32 QK + bf16 split-3 PV, long-first)
    cudaFuncSetAttribute(attn_mma_kernel,
                         cudaFuncAttributeMaxDynamicSharedMemorySize, ATT_SMEM);
    attn_mma_kernel<<<dim3(CT / 128, CB * CH), 256, ATT_SMEM>>>(
        qptr, kcache, vcache, attptr);

    // 4) output projection + bias
    gemm_tf32_kernel<<<ggrid, 512, GSMEM_BYTES>>>(attptr, Wp, bp, out, 1);
}